// round 5
// baseline (speedup 1.0000x reference)
#include <cuda_runtime.h>
#include <cstddef>

// Problem constants
#define BB   128
#define TT   1024
#define II   256
#define HH   512
#define CLIPV 5.0f

// Tiling: 32 j-tiles x 4 m-blocks = 128 persistent blocks, 128 threads each.
#define JT   16          // j columns per block
#define MB   32          // batch rows per block
#define NITER 12         // chunk-pair iterations per step (24 chunks of K=32)

// Device scratch (no cudaMalloc allowed)
__device__ float g_h[2][BB * HH];
__device__ unsigned g_arrive;
__device__ unsigned g_release;

typedef unsigned long long u64;

__device__ __forceinline__ u64 ffma2(u64 a, u64 b, u64 c) {
    u64 d;
    asm("fma.rn.f32x2 %0, %1, %2, %3;" : "=l"(d) : "l"(a), "l"(b), "l"(c));
    return d;
}
__device__ __forceinline__ float sigm(float v) { return 1.0f / (1.0f + __expf(-v)); }

// Dynamic smem layout (floats):
//   Wsm : [3 gates][768 k][16 cols]            = 36864 floats (147456 B)
//   As2 : float2 [(2 buf x 2 grp)*32 kk][33 m] =  4224 float2 ( 33792 B)
//   part: [4 gates][2 grp][512 cells]          =  4096 floats ( 16384 B)
#define W_FLOATS    (3 * 768 * 16)
#define AS_F2       (2 * 2 * 32 * 33)
#define PART_FLOATS (4 * 2 * 512)
#define SMEM_BYTES  (W_FLOATS * 4 + AS_F2 * 8 + PART_FLOATS * 4)

__global__ void __launch_bounds__(128, 1)
gru_persistent(const float* __restrict__ x,      // [B, T, I]
               const float* __restrict__ w_ih,   // [3H, I]
               const float* __restrict__ w_hh,   // [3H, H]
               const float* __restrict__ b_ih,   // [3H]
               const float* __restrict__ b_hh,   // [3H]
               float* __restrict__ out,          // [B, T, H] (+ [B,H] tail)
               int write_hlast)
{
    extern __shared__ float smem[];
    float*  Wsm  = smem;                                  // weight slice, resident all run
    float2* As2  = (float2*)(smem + W_FLOATS);            // A tiles, value-duplicated
    float*  part = smem + W_FLOATS + AS_F2 * 2;           // partial sums across K-halves

    // Small static smem: per-block combined biases, loaded once.
    // [0]=r bias (b_ih+b_hh), [1]=z bias, [2]=n h-bias (b_hh), [3]=n x-bias (b_ih)
    __shared__ float bias_sm[4][JT];

    const int tid = threadIdx.x;
    const int j0  = blockIdx.x * JT;
    const int m0  = blockIdx.y * MB;
    const unsigned nblocks = gridDim.x * gridDim.y;

    // ---- One-time: biases into smem.
    if (tid < JT) {
        const int j = j0 + tid;
        bias_sm[0][tid] = b_ih[j] + b_hh[j];
        bias_sm[1][tid] = b_ih[HH + j] + b_hh[HH + j];
        bias_sm[2][tid] = b_hh[2 * HH + j];
        bias_sm[3][tid] = b_ih[2 * HH + j];
    }

    // ---- One-time: load this block's weight slice into smem.
    // Layout Wsm[(g*768 + k)*16 + c]; k<512 -> w_hh, k>=512 -> w_ih.
    for (int gc = 0; gc < 48; gc++) {
        const int g = gc >> 4, c = gc & 15;
        const int col = g * HH + j0 + c;
        const float* __restrict__ srcH = w_hh + (size_t)col * HH;
        const float* __restrict__ srcI = w_ih + (size_t)col * II;
        for (int k = tid; k < 768; k += 128) {
            float v = (k < HH) ? srcH[k] : srcI[k - HH];
            Wsm[(g * 768 + k) * 16 + c] = v;
        }
    }
    __syncthreads();

    // Thread roles: grp 0 = warps 0-1 (K chunks 0..11, all-h region),
    //               grp 1 = warps 2-3 (K chunks 12..23: 12-15 h, 16-23 x).
    const int grp = tid >> 6;
    const int t6  = tid & 63;
    const int jp  = t6 & 7;       // j-pair (covers j0+2jp, j0+2jp+1)
    const int rg  = t6 >> 3;      // row group (4 rows: 4rg..4rg+3)

    float ra[16];                 // staging regs: 2 tiles x 1024 floats / 128 thr

    for (int t = 0; t < TT; t++) {
        const float* __restrict__ hprev = g_h[t & 1];
        float* __restrict__       hnext = g_h[(t + 1) & 1];

        u64 aR0=0,aR1=0,aR2=0,aR3=0;
        u64 aZ0=0,aZ1=0,aZ2=0,aZ3=0;
        u64 aNh0=0,aNh1=0,aNh2=0,aNh3=0;   // n-gate, h-part (multiplied by r)
        u64 aNi0=0,aNi1=0,aNi2=0,aNi3=0;   // n-gate, x-part

        // --- staging helpers (all 128 threads load both groups' tiles) ---
        #define STAGE_LOAD(ITER)                                                  \
        {   const int _i = (ITER);                                                \
            _Pragma("unroll")                                                     \
            for (int u = 0; u < 16; u++) {                                        \
                int idx = tid + u * 128;                                          \
                int g2  = idx >> 10;                                              \
                int rem = idx & 1023;                                             \
                int kk  = rem & 31;                                               \
                int m   = rem >> 5;                                               \
                int ch  = g2 ? (12 + _i) : _i;                                    \
                float v;                                                          \
                if (ch < 16) v = hprev[(m0 + m) * HH + ch * 32 + kk];             \
                else v = x[((size_t)(m0 + m) * TT + t) * II + (ch - 16) * 32 + kk];\
                ra[u] = v;                                                        \
            } }
        #define STAGE_STORE(BUF)                                                  \
        {   const int _b = (BUF);                                                 \
            _Pragma("unroll")                                                     \
            for (int u = 0; u < 16; u++) {                                        \
                int idx = tid + u * 128;                                          \
                int g2  = idx >> 10;                                              \
                int rem = idx & 1023;                                             \
                int kk  = rem & 31;                                               \
                int m   = rem >> 5;                                               \
                As2[((_b * 2 + g2) * 32 + kk) * 33 + m] = make_float2(ra[u], ra[u]);\
            } }
        // Inner K-loop: 12 FFMA2 + 7 LDS.64 per k.
        #define KLOOP(N0, N1, N2, N3, K0, TBASE)                                  \
            _Pragma("unroll")                                                     \
            for (int kk = 0; kk < 32; kk++) {                                     \
                const u64 wr = *(const u64*)(Wsm + (0*768 + (K0)+kk)*16 + 2*jp);  \
                const u64 wz = *(const u64*)(Wsm + (1*768 + (K0)+kk)*16 + 2*jp);  \
                const u64 wn = *(const u64*)(Wsm + (2*768 + (K0)+kk)*16 + 2*jp);  \
                const u64* ak = (const u64*)(As2 + ((TBASE) + kk) * 33 + 4 * rg); \
                u64 a0 = ak[0], a1 = ak[1], a2 = ak[2], a3 = ak[3];               \
                aR0 = ffma2(a0, wr, aR0);  aR1 = ffma2(a1, wr, aR1);              \
                aR2 = ffma2(a2, wr, aR2);  aR3 = ffma2(a3, wr, aR3);              \
                aZ0 = ffma2(a0, wz, aZ0);  aZ1 = ffma2(a1, wz, aZ1);              \
                aZ2 = ffma2(a2, wz, aZ2);  aZ3 = ffma2(a3, wz, aZ3);              \
                N0  = ffma2(a0, wn, N0);   N1  = ffma2(a1, wn, N1);               \
                N2  = ffma2(a2, wn, N2);   N3  = ffma2(a3, wn, N3);               \
            }

        STAGE_LOAD(0);
        STAGE_STORE(0);
        __syncthreads();

        for (int i = 0; i < NITER; i++) {
            if (i + 1 < NITER) STAGE_LOAD(i + 1);
            {
                const int buf   = i & 1;
                const int chunk = grp ? (12 + i) : i;
                const int k0    = chunk * 32;
                const int tbase = (buf * 2 + grp) * 32;
                if (chunk < 16) { KLOOP(aNh0, aNh1, aNh2, aNh3, k0, tbase); }
                else            { KLOOP(aNi0, aNi1, aNi2, aNi3, k0, tbase); }
            }
            if (i + 1 < NITER) STAGE_STORE((i + 1) & 1);
            __syncthreads();
        }

        // --- write partials: part[(gate*2 + grp)*512 + cell], cell = m*16 + jj ---
        {
            u64 r_[4]  = {aR0, aR1, aR2, aR3};
            u64 z_[4]  = {aZ0, aZ1, aZ2, aZ3};
            u64 nh_[4] = {aNh0, aNh1, aNh2, aNh3};
            u64 ni_[4] = {aNi0, aNi1, aNi2, aNi3};
            #pragma unroll
            for (int r = 0; r < 4; r++) {
                int cell = (4 * rg + r) * 16 + 2 * jp;
                *(u64*)&part[(0 * 2 + grp) * 512 + cell] = r_[r];
                *(u64*)&part[(1 * 2 + grp) * 512 + cell] = z_[r];
                *(u64*)&part[(2 * 2 + grp) * 512 + cell] = nh_[r];
                *(u64*)&part[(3 * 2 + grp) * 512 + cell] = ni_[r];
            }
        }
        __syncthreads();

        // --- epilogue: gates + state update, 4 cells per thread ---
        #pragma unroll
        for (int u = 0; u < 4; u++) {
            int cell = tid + u * 128;
            int m = cell >> 4, jj = cell & 15;
            int b = m0 + m, j = j0 + jj;
            float rsum = part[(0*2+0)*512 + cell] + part[(0*2+1)*512 + cell]
                       + bias_sm[0][jj];
            float zsum = part[(1*2+0)*512 + cell] + part[(1*2+1)*512 + cell]
                       + bias_sm[1][jj];
            float nh   = part[(2*2+0)*512 + cell] + part[(2*2+1)*512 + cell]
                       + bias_sm[2][jj];
            float ni   = part[(3*2+1)*512 + cell] + bias_sm[3][jj];
            float r_ = sigm(rsum);
            float z_ = sigm(zsum);
            float n_ = tanhf(ni + r_ * nh);
            float hold = hprev[b * HH + j];
            float hn = (1.0f - z_) * n_ + z_ * hold;
            hn = fminf(CLIPV, fmaxf(-CLIPV, hn));
            hnext[b * HH + j] = hn;
            out[((size_t)b * TT + t) * HH + j] = hn;
            if (write_hlast && t == TT - 1)
                out[(size_t)BB * TT * HH + b * HH + j] = hn;
        }

        // --- grid barrier (128 co-resident blocks; 1 block/SM by smem) ---
        __syncthreads();
        if (tid == 0) {
            __threadfence();
            unsigned prev = atomicAdd(&g_arrive, 1u);
            unsigned target = (unsigned)(t + 1) * nblocks;
            if (prev + 1u == target) {
                atomicExch(&g_release, (unsigned)(t + 1));
            } else {
                while (*(volatile unsigned*)&g_release < (unsigned)(t + 1))
                    __nanosleep(64);
            }
            __threadfence();
        }
        __syncthreads();

        #undef STAGE_LOAD
        #undef STAGE_STORE
        #undef KLOOP
    }
}

// Init: tile h0 [1,H] -> g_h[0] as [B,H]; reset barrier counters.
__global__ void init_h(const float* __restrict__ h0) {
    int i = blockIdx.x * 256 + threadIdx.x;
    if (i < BB * HH) g_h[0][i] = h0[i & (HH - 1)];
    if (i == 0) { g_arrive = 0u; g_release = 0u; }
}

extern "C" void kernel_launch(void* const* d_in, const int* in_sizes, int n_in,
                              void* d_out, int out_size) {
    const float* x    = (const float*)d_in[0];
    const float* h0   = (const float*)d_in[1];
    const float* w_ih = (const float*)d_in[2];
    const float* w_hh = (const float*)d_in[3];
    const float* b_ih = (const float*)d_in[4];
    const float* b_hh = (const float*)d_in[5];
    float* out = (float*)d_out;

    cudaFuncSetAttribute(gru_persistent,
                         cudaFuncAttributeMaxDynamicSharedMemorySize, SMEM_BYTES);

    init_h<<<(BB * HH + 255) / 256, 256>>>(h0);

    const size_t main_elems = (size_t)BB * TT * HH;
    int write_hlast = ((size_t)out_size >= main_elems + (size_t)BB * HH) ? 1 : 0;

    dim3 grid(HH / JT, BB / MB);   // 32 x 4 = 128 blocks, 1 per SM
    gru_persistent<<<grid, 128, SMEM_BYTES>>>(x, w_ih, w_hh, b_ih, b_hh, out,
                                              write_hlast);
}